// round 11
// baseline (speedup 1.0000x reference)
#include <cuda_runtime.h>
#include <cuda_fp16.h>
#include <cstdint>

// Problem sizes (fixed by the reference)
#define NNODES 50000
#define NREL   8
#define DIM    128
#define NEDGE  800000
#define NTRIP  100000
#define KTOT   1152          // NREL*DIM + DIM (root folded as 9th block)
#define K0LIM  1024          // NREL*DIM
#define NSEG   (NNODES * NREL)          // 400000
#define NBLK   ((NSEG + 1023) / 1024)   // 391

// ---------------- scratch (static device globals; no allocs allowed) -------
__device__ __align__(16) __half g_sum16[(size_t)NSEG * DIM];     // 102.4 MB fp16 means
__device__ __align__(16) __half g_e16[(size_t)NNODES * DIM];     // 12.8 MB emb fp16
__device__ __align__(16) __half g_h116[(size_t)NNODES * DIM];    // 12.8 MB
__device__ __align__(16) __half g_h216[(size_t)NNODES * DIM];    // 12.8 MB
__device__ __align__(16) __half g_WT016[(size_t)DIM * KTOT];     // (W0||root0)^T fp16
__device__ __align__(16) __half g_WT116[(size_t)DIM * KTOT];
__device__ int g_cnt[NSEG];
__device__ int g_off[NSEG];
__device__ int g_fill[NSEG];
__device__ int g_csr[NEDGE];
__device__ int g_bsum[NBLK];

__device__ __forceinline__ uint32_t smem_u32(const void* p) {
    uint32_t a;
    asm("{ .reg .u64 t; cvta.to.shared.u64 t, %1; cvt.u32.u64 %0, t; }"
        : "=r"(a) : "l"(p));
    return a;
}
__device__ __forceinline__ void cp16(uint32_t dst, const void* src, bool pred) {
    int sz = pred ? 16 : 0;
    asm volatile("cp.async.cg.shared.global [%0], [%1], 16, %2;"
                 :: "r"(dst), "l"(src), "r"(sz) : "memory");
}

// ---------------- fused prep: emb->fp16, W transpose, cnt/fill zero --------
// grid = 3200 + 2304 + 391 blocks
#define PREP_CONV 3200            // conv: 3200 blocks x 256 thr x 2 uint2
#define PREP_TW   (2 * KTOT)      // 2304 transpose blocks x 128 thr
__global__ void prep_kernel(const float* __restrict__ emb,
                            const float* __restrict__ W0,
                            const float* __restrict__ root0,
                            const float* __restrict__ W1,
                            const float* __restrict__ root1) {
    int b = blockIdx.x;
    if (b < PREP_CONV) {
        const size_t n4 = (size_t)NNODES * DIM / 4;    // 1.6M uint2
        for (size_t i = (size_t)b * 256 * 2 + threadIdx.x;
             i < n4 && i < (size_t)(b + 1) * 512; i += 256) {
            float4 v = reinterpret_cast<const float4*>(emb)[i];
            __half2 lo = __floats2half2_rn(v.x, v.y);
            __half2 hi = __floats2half2_rn(v.z, v.w);
            uint2 o;
            o.x = *reinterpret_cast<uint32_t*>(&lo);
            o.y = *reinterpret_cast<uint32_t*>(&hi);
            reinterpret_cast<uint2*>(g_e16)[i] = o;
        }
    } else if (b < PREP_CONV + PREP_TW) {
        if (threadIdx.x < 128) {
            int bb = b - PREP_CONV;
            int layer = bb / KTOT;
            int k = bb % KTOT;
            const float* src;
            if (layer == 0)
                src = (k < K0LIM) ? (W0 + (size_t)k * DIM)
                                  : (root0 + (size_t)(k - K0LIM) * DIM);
            else
                src = (k < K0LIM) ? (W1 + (size_t)k * DIM)
                                  : (root1 + (size_t)(k - K0LIM) * DIM);
            float v = src[threadIdx.x];
            __half* dst = layer ? g_WT116 : g_WT016;
            dst[(size_t)threadIdx.x * KTOT + k] = __float2half_rn(v);
        }
    } else {
        int bb = b - PREP_CONV - PREP_TW;
        for (int i = bb * 1024 + threadIdx.x;
             i < NSEG && i < (bb + 1) * 1024; i += 256) {
            g_cnt[i] = 0;
            g_fill[i] = 0;
        }
    }
}

// ---------------- CSR build -----------------------------------------------
__global__ void csr_hist(const int* __restrict__ ei,
                         const int* __restrict__ et) {
    int e = blockIdx.x * blockDim.x + threadIdx.x;
    if (e >= NEDGE) return;
    int seg = ei[NEDGE + e] * NREL + et[e];
    atomicAdd(&g_cnt[seg], 1);
}
__global__ void csr_bsum() {  // grid NBLK x 1024
    __shared__ int sh[1024];
    int gid = blockIdx.x * 1024 + threadIdx.x;
    sh[threadIdx.x] = (gid < NSEG) ? g_cnt[gid] : 0;
    __syncthreads();
    for (int s = 512; s > 0; s >>= 1) {
        if (threadIdx.x < s) sh[threadIdx.x] += sh[threadIdx.x + s];
        __syncthreads();
    }
    if (threadIdx.x == 0) g_bsum[blockIdx.x] = sh[0];
}
__global__ void csr_off() {  // grid NBLK x 1024; folds bsum prefix in
    __shared__ int sh[1024];
    __shared__ int sbase;
    int gid = blockIdx.x * 1024 + threadIdx.x;
    int v = (gid < NSEG) ? g_cnt[gid] : 0;
    sh[threadIdx.x] = v;
    // warp 0: prefix over preceding block sums (<= 391 ints)
    if (threadIdx.x < 32) {
        int s = 0;
        for (int i = threadIdx.x; i < blockIdx.x; i += 32)
            s += g_bsum[i];
#pragma unroll
        for (int off = 16; off; off >>= 1)
            s += __shfl_xor_sync(0xFFFFFFFFu, s, off);
        if (threadIdx.x == 0) sbase = s;
    }
    __syncthreads();
    for (int ofs = 1; ofs < 1024; ofs <<= 1) {
        int t = (threadIdx.x >= ofs) ? sh[threadIdx.x - ofs] : 0;
        __syncthreads();
        sh[threadIdx.x] += t;
        __syncthreads();
    }
    if (gid < NSEG) g_off[gid] = sbase + sh[threadIdx.x] - v;
}
__global__ void csr_fill(const int* __restrict__ ei,
                         const int* __restrict__ et) {
    int e = blockIdx.x * blockDim.x + threadIdx.x;
    if (e >= NEDGE) return;
    int seg = ei[NEDGE + e] * NREL + et[e];
    int pos = g_off[seg] + atomicAdd(&g_fill[seg], 1);
    g_csr[pos] = ei[e];
}

// ---------------- aggregate: warp per segment, fp16 in/out -----------------
__global__ __launch_bounds__(256) void aggregate_kernel(int useG) {
    int w    = (blockIdx.x * blockDim.x + threadIdx.x) >> 5;
    int lane = threadIdx.x & 31;
    if (w >= NSEG) return;
    const __half* __restrict__ h = useG ? g_h116 : g_e16;

    int beg = g_off[w];
    int c   = g_cnt[w];
    float4 acc = make_float4(0.f, 0.f, 0.f, 0.f);
    for (int base = 0; base < c; base += 4) {
        int s[4];
#pragma unroll
        for (int j = 0; j < 4; ++j)
            s[j] = (base + j < c) ? g_csr[beg + base + j] : -1;
#pragma unroll
        for (int j = 0; j < 4; ++j) {
            if (s[j] >= 0) {
                uint2 t = reinterpret_cast<const uint2*>(
                    h + (size_t)s[j] * DIM)[lane];
                float2 f0 = __half22float2(*reinterpret_cast<__half2*>(&t.x));
                float2 f1 = __half22float2(*reinterpret_cast<__half2*>(&t.y));
                acc.x += f0.x; acc.y += f0.y; acc.z += f1.x; acc.w += f1.y;
            }
        }
    }
    float inv = 1.0f / (float)max(c, 1);
    __half2 o0 = __floats2half2_rn(acc.x * inv, acc.y * inv);
    __half2 o1 = __floats2half2_rn(acc.z * inv, acc.w * inv);
    uint2 r;
    r.x = *reinterpret_cast<uint32_t*>(&o0);
    r.y = *reinterpret_cast<uint32_t*>(&o1);
    asm volatile("st.global.cs.v2.u32 [%0], {%1,%2};"
                 :: "l"(reinterpret_cast<uint2*>(g_sum16 + (size_t)w * DIM) + lane),
                    "r"(r.x), "r"(r.y) : "memory");
}

// ---------------- fp16 mma.sync RGCN layer GEMM (cp.async pipeline) --------
// BM=64, BN=128, BK=64, 4-stage cp.async. 8 warps 4x2, warp tile 16x64.
#define BM      64
#define KCH     64
#define NCHUNK  (KTOT / KCH)            // 18
#define LDPH    72                      // padded smem row stride (halfs)
#define BUF_H   ((BM + 128) * LDPH)     // halfs per stage (A 64 rows + B 128 rows)
#define NSTAGE  4
#define SMEM_TOT (NSTAGE * BUF_H * 2)   // 110592 B

__device__ __forceinline__ void mma_f16(float* c, const uint32_t* a,
                                        const uint32_t* b) {
    asm volatile(
        "mma.sync.aligned.m16n8k16.row.col.f32.f16.f16.f32 "
        "{%0,%1,%2,%3}, {%4,%5,%6,%7}, {%8,%9}, {%0,%1,%2,%3};"
        : "+f"(c[0]), "+f"(c[1]), "+f"(c[2]), "+f"(c[3])
        : "r"(a[0]), "r"(a[1]), "r"(a[2]), "r"(a[3]), "r"(b[0]), "r"(b[1]));
}

__global__ __launch_bounds__(256, 2) void rgcn_gemm_mma(
    int useGin, int wtSel, const float* __restrict__ bias, int outSel)
{
    extern __shared__ __half smemh[];
    const uint32_t smemBase = smem_u32(smemh);
    const int tid  = threadIdx.x;
    const int wid  = tid >> 5;
    const int lane = tid & 31;
    const int g    = lane >> 2;
    const int t4   = lane & 3;
    const int wr   = wid & 3;        // warp row (M: 4 x 16)
    const int wc   = wid >> 2;       // warp col (N: 2 x 64)
    const int row0 = blockIdx.x * BM;

    const __half* __restrict__ hin = useGin ? g_h116 : g_e16;
    const __half* __restrict__ WT  = wtSel ? g_WT116 : g_WT016;
    __half* __restrict__ hout = outSel ? g_h216 : g_h116;

    float acc[8][4];
#pragma unroll
    for (int nt = 0; nt < 8; ++nt)
#pragma unroll
        for (int j = 0; j < 4; ++j) acc[nt][j] = 0.f;

    // ---- issue cp.async loads for chunk c into stage buf ----
    // A: 64 rows x 8 granules = 512; B: 128 rows x 8 granules = 1024. 1536 tot.
    auto issue = [&](int buf, int c) {
        const int k0 = c * KCH;
        const bool isSum = (k0 < K0LIM);
        uint32_t aBase = smemBase + (uint32_t)(buf * BUF_H) * 2u;
        uint32_t bBase = aBase + (uint32_t)BM * LDPH * 2u;
#pragma unroll
        for (int it = 0; it < 6; ++it) {
            int idx = tid + it * 256;        // 0..1535
            if (idx < 512) {
                int m = idx >> 3, q = idx & 7;
                int n = row0 + m;
                bool ok = (n < NNODES);
                int nc = ok ? n : (NNODES - 1);
                const __half* srcA = isSum
                    ? (g_sum16 + (size_t)nc * K0LIM + k0 + q * 8)
                    : (hin + (size_t)nc * DIM + (k0 - K0LIM) + q * 8);
                cp16(aBase + (uint32_t)(m * LDPH + q * 8) * 2u, srcA, ok);
            } else {
                int j = idx - 512;
                int m = j >> 3, q = j & 7;
                cp16(bBase + (uint32_t)(m * LDPH + q * 8) * 2u,
                     WT + (size_t)m * KTOT + k0 + q * 8, true);
            }
        }
        asm volatile("cp.async.commit_group;" ::: "memory");
    };

    // ---- compute one k-chunk (4 k16-steps) from stage buf ----
    auto compute = [&](int buf) {
        const __half* smA = smemh + buf * BUF_H;
        const __half* smB = smA + BM * LDPH;
#pragma unroll
        for (int ks = 0; ks < 4; ++ks) {
            const int kk = ks * 16;
            uint32_t a[4], b[8][2];
            {
                int r0 = wr * 16 + g;
                a[0] = *reinterpret_cast<const uint32_t*>(
                    smA + (r0)     * LDPH + kk + 2 * t4);
                a[1] = *reinterpret_cast<const uint32_t*>(
                    smA + (r0 + 8) * LDPH + kk + 2 * t4);
                a[2] = *reinterpret_cast<const uint32_t*>(
                    smA + (r0)     * LDPH + kk + 8 + 2 * t4);
                a[3] = *reinterpret_cast<const uint32_t*>(
                    smA + (r0 + 8) * LDPH + kk + 8 + 2 * t4);
            }
#pragma unroll
            for (int nt = 0; nt < 8; ++nt) {
                int nn = wc * 64 + nt * 8 + g;
                b[nt][0] = *reinterpret_cast<const uint32_t*>(
                    smB + nn * LDPH + kk + 2 * t4);
                b[nt][1] = *reinterpret_cast<const uint32_t*>(
                    smB + nn * LDPH + kk + 8 + 2 * t4);
            }
#pragma unroll
            for (int nt = 0; nt < 8; ++nt)
                mma_f16(acc[nt], a, b[nt]);
        }
    };

    // ---- 4-stage pipeline ----
    issue(0, 0);
    issue(1, 1);
    issue(2, 2);
    for (int c = 0; c < NCHUNK; ++c) {
        if (c + 3 < NCHUNK) {
            issue((c + 3) % NSTAGE, c + 3);
            asm volatile("cp.async.wait_group 3;" ::: "memory");
        } else if (c + 2 < NCHUNK) {
            asm volatile("cp.async.wait_group 2;" ::: "memory");
        } else if (c + 1 < NCHUNK) {
            asm volatile("cp.async.wait_group 1;" ::: "memory");
        } else {
            asm volatile("cp.async.wait_group 0;" ::: "memory");
        }
        __syncthreads();
        compute(c % NSTAGE);
        __syncthreads();
    }

    // ---- epilogue: bias + relu, write fp16 ----
    float2 bb[8];
#pragma unroll
    for (int nt = 0; nt < 8; ++nt) {
        int col = wc * 64 + nt * 8 + t4 * 2;
        bb[nt].x = __ldg(bias + col);
        bb[nt].y = __ldg(bias + col + 1);
    }
    {
        int r0 = row0 + wr * 16 + g;
#pragma unroll
        for (int half = 0; half < 2; ++half) {
            int n = r0 + half * 8;
            if (n < NNODES) {
                __half* dst = hout + (size_t)n * DIM;
#pragma unroll
                for (int nt = 0; nt < 8; ++nt) {
                    int col = wc * 64 + nt * 8 + t4 * 2;
                    float ox = fmaxf(acc[nt][half * 2 + 0] + bb[nt].x, 0.f);
                    float oy = fmaxf(acc[nt][half * 2 + 1] + bb[nt].y, 0.f);
                    *reinterpret_cast<__half2*>(dst + col) =
                        __floats2half2_rn(ox, oy);
                }
            }
        }
    }
}

// ---------------- DistMult score: one warp per triple (fp16 h) ------------
__global__ void score_kernel(const float* __restrict__ rel_emb,
                             const int* __restrict__ head,
                             const int* __restrict__ rel,
                             const int* __restrict__ tail,
                             float* __restrict__ out) {
    int t    = (blockIdx.x * blockDim.x + threadIdx.x) >> 5;
    int lane = threadIdx.x & 31;
    if (t >= NTRIP) return;
    uint2 ar = reinterpret_cast<const uint2*>(
        g_h216 + (size_t)head[t] * DIM)[lane];
    uint2 br = reinterpret_cast<const uint2*>(
        g_h216 + (size_t)tail[t] * DIM)[lane];
    const float4 r = reinterpret_cast<const float4*>(
        rel_emb + (size_t)rel[t] * DIM)[lane];
    float2 a0 = __half22float2(*reinterpret_cast<__half2*>(&ar.x));
    float2 a1 = __half22float2(*reinterpret_cast<__half2*>(&ar.y));
    float2 b0 = __half22float2(*reinterpret_cast<__half2*>(&br.x));
    float2 b1 = __half22float2(*reinterpret_cast<__half2*>(&br.y));
    float s = a0.x * r.x * b0.x + a0.y * r.y * b0.y
            + a1.x * r.z * b1.x + a1.y * r.w * b1.y;
#pragma unroll
    for (int off = 16; off; off >>= 1)
        s += __shfl_xor_sync(0xFFFFFFFFu, s, off);
    if (lane == 0) out[t] = s;
}

// ---------------- launcher -------------------------------------------------
extern "C" void kernel_launch(void* const* d_in, const int* in_sizes, int n_in,
                              void* d_out, int out_size) {
    const float* emb   = (const float*)d_in[0];
    const float* W0    = (const float*)d_in[1];
    const float* root0 = (const float*)d_in[2];
    const float* b0    = (const float*)d_in[3];
    const float* W1    = (const float*)d_in[4];
    const float* root1 = (const float*)d_in[5];
    const float* b1    = (const float*)d_in[6];
    const float* relE  = (const float*)d_in[7];
    const int*   ei    = (const int*)d_in[8];
    const int*   et    = (const int*)d_in[9];
    const int*   hidx  = (const int*)d_in[10];
    const int*   ridx  = (const int*)d_in[11];
    const int*   tidx  = (const int*)d_in[12];
    float*       out   = (float*)d_out;

    static int smemSet = 0;
    if (!smemSet) {
        cudaFuncSetAttribute(rgcn_gemm_mma,
                             cudaFuncAttributeMaxDynamicSharedMemorySize,
                             SMEM_TOT);
        smemSet = 1;
    }

    const int prepGrid  = PREP_CONV + PREP_TW + NBLK;   // 5895
    const int edgeGrid  = (NEDGE + 255) / 256;          // 3125
    const int aggGrid   = (NSEG * 32 + 255) / 256;      // 50000
    const int gemmGrid  = (NNODES + BM - 1) / BM;       // 782
    const int scoreGrid = (NTRIP * 32 + 255) / 256;     // 12500

    prep_kernel<<<prepGrid, 256>>>(emb, W0, root0, W1, root1);

    // ----- CSR build (shared by both layers) -----
    csr_hist<<<edgeGrid, 256>>>(ei, et);
    csr_bsum<<<NBLK, 1024>>>();
    csr_off<<<NBLK, 1024>>>();
    csr_fill<<<edgeGrid, 256>>>(ei, et);

    // ----- layer 0 -----
    aggregate_kernel<<<aggGrid, 256>>>(0);
    rgcn_gemm_mma<<<gemmGrid, 256, SMEM_TOT>>>(0, /*wt*/0, b0, /*out*/0);

    // ----- layer 1 -----
    aggregate_kernel<<<aggGrid, 256>>>(1);
    rgcn_gemm_mma<<<gemmGrid, 256, SMEM_TOT>>>(1, /*wt*/1, b1, /*out*/1);

    // ----- DistMult score -----
    score_kernel<<<scoreGrid, 256>>>(relE, hidx, ridx, tidx, out);
}

// round 12
// speedup vs baseline: 1.0985x; 1.0985x over previous
#include <cuda_runtime.h>
#include <cuda_fp16.h>
#include <cstdint>

// Problem sizes (fixed by the reference)
#define NNODES 50000
#define NREL   8
#define DIM    128
#define NEDGE  800000
#define NTRIP  100000
#define KTOT   1152          // NREL*DIM + DIM (root folded as 9th block)
#define K0LIM  1024          // NREL*DIM
#define NSEG   (NNODES * NREL)          // 400000
#define NBLK   ((NSEG + 1023) / 1024)   // 391

// ---------------- scratch (static device globals; no allocs allowed) -------
__device__ __align__(16) __half g_sum16[(size_t)NSEG * DIM];     // 102.4 MB fp16 means
__device__ __align__(16) __half g_e16[(size_t)NNODES * DIM];     // 12.8 MB emb fp16
__device__ __align__(16) __half g_h116[(size_t)NNODES * DIM];    // 12.8 MB
__device__ __align__(16) __half g_h216[(size_t)NNODES * DIM];    // 12.8 MB
__device__ __align__(16) __half g_WT016[(size_t)DIM * KTOT];     // (W0||root0)^T fp16
__device__ __align__(16) __half g_WT116[(size_t)DIM * KTOT];
__device__ int g_cnt[NSEG];
__device__ int g_off[NSEG];
__device__ int g_fill[NSEG];
__device__ int g_csr[NEDGE];
__device__ int g_cursor;

__device__ __forceinline__ uint32_t smem_u32(const void* p) {
    uint32_t a;
    asm("{ .reg .u64 t; cvta.to.shared.u64 t, %1; cvt.u32.u64 %0, t; }"
        : "=r"(a) : "l"(p));
    return a;
}
__device__ __forceinline__ void cp16(uint32_t dst, const void* src, bool pred) {
    int sz = pred ? 16 : 0;
    asm volatile("cp.async.cg.shared.global [%0], [%1], 16, %2;"
                 :: "r"(dst), "l"(src), "r"(sz) : "memory");
}

// ---------------- emb -> fp16 ----------------------------------------------
__global__ void conv_emb(const float* __restrict__ emb) {
    const size_t n4 = (size_t)NNODES * DIM / 4;
    for (size_t i = (size_t)blockIdx.x * blockDim.x + threadIdx.x;
         i < n4; i += (size_t)gridDim.x * blockDim.x) {
        float4 v = reinterpret_cast<const float4*>(emb)[i];
        __half2 lo = __floats2half2_rn(v.x, v.y);
        __half2 hi = __floats2half2_rn(v.z, v.w);
        uint2 o;
        o.x = *reinterpret_cast<uint32_t*>(&lo);
        o.y = *reinterpret_cast<uint32_t*>(&hi);
        reinterpret_cast<uint2*>(g_e16)[i] = o;
    }
}

// ---------------- W||root transpose -> fp16 --------------------------------
__global__ void transpose_w(const float* __restrict__ W0,
                            const float* __restrict__ root0,
                            const float* __restrict__ W1,
                            const float* __restrict__ root1) {
    int b = blockIdx.x;
    int layer = b / KTOT;
    int k = b % KTOT;
    const float* src;
    if (layer == 0)
        src = (k < K0LIM) ? (W0 + (size_t)k * DIM) : (root0 + (size_t)(k - K0LIM) * DIM);
    else
        src = (k < K0LIM) ? (W1 + (size_t)k * DIM) : (root1 + (size_t)(k - K0LIM) * DIM);
    float v = src[threadIdx.x];
    __half* dst = layer ? g_WT116 : g_WT016;
    dst[(size_t)threadIdx.x * KTOT + k] = __float2half_rn(v);
}

// ---------------- CSR build -----------------------------------------------
__global__ void csr_zero() {
    for (int i = blockIdx.x * blockDim.x + threadIdx.x; i < NSEG;
         i += gridDim.x * blockDim.x) {
        g_cnt[i] = 0;
        g_fill[i] = 0;
    }
    if (blockIdx.x == 0 && threadIdx.x == 0) g_cursor = 0;
}
__global__ void csr_hist(const int* __restrict__ ei,
                         const int* __restrict__ et) {
    int e = blockIdx.x * blockDim.x + threadIdx.x;
    if (e >= NEDGE) return;
    int seg = ei[NEDGE + e] * NREL + et[e];
    atomicAdd(&g_cnt[seg], 1);
}
// single-kernel offsets: in-block inclusive scan + atomic cursor for base.
// Segment ranges are disjoint/correctly sized; their order in g_csr is
// irrelevant to correctness (g_off indexes by segment id).
__global__ void csr_off() {  // grid NBLK x 1024
    __shared__ int sh[1024];
    __shared__ int sbase;
    int gid = blockIdx.x * 1024 + threadIdx.x;
    int v = (gid < NSEG) ? g_cnt[gid] : 0;
    sh[threadIdx.x] = v;
    __syncthreads();
    for (int ofs = 1; ofs < 1024; ofs <<= 1) {
        int t = (threadIdx.x >= ofs) ? sh[threadIdx.x - ofs] : 0;
        __syncthreads();
        sh[threadIdx.x] += t;
        __syncthreads();
    }
    if (threadIdx.x == 1023) sbase = atomicAdd(&g_cursor, sh[1023]);
    __syncthreads();
    if (gid < NSEG) g_off[gid] = sbase + sh[threadIdx.x] - v;
}
__global__ void csr_fill(const int* __restrict__ ei,
                         const int* __restrict__ et) {
    int e = blockIdx.x * blockDim.x + threadIdx.x;
    if (e >= NEDGE) return;
    int seg = ei[NEDGE + e] * NREL + et[e];
    int pos = g_off[seg] + atomicAdd(&g_fill[seg], 1);
    g_csr[pos] = ei[e];
}

// ---------------- aggregate: warp per segment, fp16 in/out -----------------
__global__ __launch_bounds__(256) void aggregate_kernel(int useG) {
    int w    = (blockIdx.x * blockDim.x + threadIdx.x) >> 5;
    int lane = threadIdx.x & 31;
    if (w >= NSEG) return;
    const __half* __restrict__ h = useG ? g_h116 : g_e16;

    int beg = g_off[w];
    int c   = g_cnt[w];
    float4 acc = make_float4(0.f, 0.f, 0.f, 0.f);
    for (int base = 0; base < c; base += 4) {
        int s[4];
#pragma unroll
        for (int j = 0; j < 4; ++j)
            s[j] = (base + j < c) ? g_csr[beg + base + j] : -1;
#pragma unroll
        for (int j = 0; j < 4; ++j) {
            if (s[j] >= 0) {
                uint2 t = reinterpret_cast<const uint2*>(
                    h + (size_t)s[j] * DIM)[lane];
                float2 f0 = __half22float2(*reinterpret_cast<__half2*>(&t.x));
                float2 f1 = __half22float2(*reinterpret_cast<__half2*>(&t.y));
                acc.x += f0.x; acc.y += f0.y; acc.z += f1.x; acc.w += f1.y;
            }
        }
    }
    float inv = 1.0f / (float)max(c, 1);
    __half2 o0 = __floats2half2_rn(acc.x * inv, acc.y * inv);
    __half2 o1 = __floats2half2_rn(acc.z * inv, acc.w * inv);
    uint2 r;
    r.x = *reinterpret_cast<uint32_t*>(&o0);
    r.y = *reinterpret_cast<uint32_t*>(&o1);
    asm volatile("st.global.cs.v2.u32 [%0], {%1,%2};"
                 :: "l"(reinterpret_cast<uint2*>(g_sum16 + (size_t)w * DIM) + lane),
                    "r"(r.x), "r"(r.y) : "memory");
}

// ---------------- fp16 mma.sync RGCN layer GEMM (cp.async pipeline) --------
// out[n,:] = relu( [g_sum16(means) || h16[n,:]] @ Wcat + bias )
// BM=128, BN=128, BK=64, 3-stage cp.async. 8 warps 4x2, warp tile 32x64.
#define KCH     64
#define NCHUNK  (KTOT / KCH)            // 18
#define LDPH    72                      // padded smem row stride (halfs)
#define BUF_H   (2 * 128 * LDPH)        // halfs per stage (A+B)
#define NSTAGE  3
#define SMEM_TOT (NSTAGE * BUF_H * 2)   // 110592 B

__device__ __forceinline__ void mma_f16(float* c, const uint32_t* a,
                                        const uint32_t* b) {
    asm volatile(
        "mma.sync.aligned.m16n8k16.row.col.f32.f16.f16.f32 "
        "{%0,%1,%2,%3}, {%4,%5,%6,%7}, {%8,%9}, {%0,%1,%2,%3};"
        : "+f"(c[0]), "+f"(c[1]), "+f"(c[2]), "+f"(c[3])
        : "r"(a[0]), "r"(a[1]), "r"(a[2]), "r"(a[3]), "r"(b[0]), "r"(b[1]));
}

__global__ __launch_bounds__(256, 2) void rgcn_gemm_mma(
    int useGin, int wtSel, const float* __restrict__ bias, int outSel)
{
    extern __shared__ __half smemh[];
    const uint32_t smemBase = smem_u32(smemh);
    const int tid  = threadIdx.x;
    const int wid  = tid >> 5;
    const int lane = tid & 31;
    const int g    = lane >> 2;
    const int t4   = lane & 3;
    const int wr   = wid & 3;        // warp row (M: 4 x 32)
    const int wc   = wid >> 2;       // warp col (N: 2 x 64)
    const int row0 = blockIdx.x * 128;

    const __half* __restrict__ hin = useGin ? g_h116 : g_e16;
    const __half* __restrict__ WT  = wtSel ? g_WT116 : g_WT016;
    __half* __restrict__ hout = outSel ? g_h216 : g_h116;

    float acc[2][8][4];
#pragma unroll
    for (int mt = 0; mt < 2; ++mt)
#pragma unroll
        for (int nt = 0; nt < 8; ++nt)
#pragma unroll
            for (int j = 0; j < 4; ++j) acc[mt][nt][j] = 0.f;

    // ---- issue cp.async loads for chunk c into stage buf ----
    auto issue = [&](int buf, int c) {
        const int k0 = c * KCH;
        const bool isSum = (k0 < K0LIM);
        uint32_t aBase = smemBase + (uint32_t)(buf * BUF_H) * 2u;
        uint32_t bBase = aBase + 128u * LDPH * 2u;
#pragma unroll
        for (int it = 0; it < 8; ++it) {
            int idx = tid + it * 256;        // 0..2047
            int m = (idx & 1023) >> 3;
            int q = idx & 7;
            uint32_t off = (uint32_t)(m * LDPH + q * 8) * 2u;
            if (idx < 1024) {
                int n = row0 + m;
                bool ok = (n < NNODES);
                int nc = ok ? n : (NNODES - 1);
                const __half* srcA = isSum
                    ? (g_sum16 + (size_t)nc * K0LIM + k0 + q * 8)
                    : (hin + (size_t)nc * DIM + (k0 - K0LIM) + q * 8);
                cp16(aBase + off, srcA, ok);
            } else {
                cp16(bBase + off, WT + (size_t)m * KTOT + k0 + q * 8, true);
            }
        }
        asm volatile("cp.async.commit_group;" ::: "memory");
    };

    // ---- compute one k-chunk (4 k16-steps) from stage buf ----
    auto compute = [&](int buf) {
        const __half* smA = smemh + buf * BUF_H;
        const __half* smB = smA + 128 * LDPH;
#pragma unroll
        for (int ks = 0; ks < 4; ++ks) {
            const int kk = ks * 16;
            uint32_t a[2][4], b[8][2];
#pragma unroll
            for (int mt = 0; mt < 2; ++mt) {
                int r0 = wr * 32 + mt * 16 + g;
                a[mt][0] = *reinterpret_cast<const uint32_t*>(
                    smA + (r0)     * LDPH + kk + 2 * t4);
                a[mt][1] = *reinterpret_cast<const uint32_t*>(
                    smA + (r0 + 8) * LDPH + kk + 2 * t4);
                a[mt][2] = *reinterpret_cast<const uint32_t*>(
                    smA + (r0)     * LDPH + kk + 8 + 2 * t4);
                a[mt][3] = *reinterpret_cast<const uint32_t*>(
                    smA + (r0 + 8) * LDPH + kk + 8 + 2 * t4);
            }
#pragma unroll
            for (int nt = 0; nt < 8; ++nt) {
                int nn = wc * 64 + nt * 8 + g;
                b[nt][0] = *reinterpret_cast<const uint32_t*>(
                    smB + nn * LDPH + kk + 2 * t4);
                b[nt][1] = *reinterpret_cast<const uint32_t*>(
                    smB + nn * LDPH + kk + 8 + 2 * t4);
            }
#pragma unroll
            for (int mt = 0; mt < 2; ++mt)
#pragma unroll
                for (int nt = 0; nt < 8; ++nt)
                    mma_f16(acc[mt][nt], a[mt], b[nt]);
        }
    };

    // ---- 3-stage pipeline ----
    issue(0, 0);
    issue(1, 1);
    for (int c = 0; c < NCHUNK; ++c) {
        if (c + 2 < NCHUNK) {
            issue((c + 2) % NSTAGE, c + 2);
            asm volatile("cp.async.wait_group 2;" ::: "memory");
        } else if (c + 1 < NCHUNK) {
            asm volatile("cp.async.wait_group 1;" ::: "memory");
        } else {
            asm volatile("cp.async.wait_group 0;" ::: "memory");
        }
        __syncthreads();
        compute(c % NSTAGE);
        __syncthreads();
    }

    // ---- epilogue: bias + relu, write fp16 ----
    float2 bb[8];
#pragma unroll
    for (int nt = 0; nt < 8; ++nt) {
        int col = wc * 64 + nt * 8 + t4 * 2;
        bb[nt].x = __ldg(bias + col);
        bb[nt].y = __ldg(bias + col + 1);
    }
#pragma unroll
    for (int mt = 0; mt < 2; ++mt) {
        int r0 = row0 + wr * 32 + mt * 16 + g;
#pragma unroll
        for (int half = 0; half < 2; ++half) {
            int n = r0 + half * 8;
            if (n < NNODES) {
                __half* dst = hout + (size_t)n * DIM;
#pragma unroll
                for (int nt = 0; nt < 8; ++nt) {
                    int col = wc * 64 + nt * 8 + t4 * 2;
                    float ox = fmaxf(acc[mt][nt][half * 2 + 0] + bb[nt].x, 0.f);
                    float oy = fmaxf(acc[mt][nt][half * 2 + 1] + bb[nt].y, 0.f);
                    *reinterpret_cast<__half2*>(dst + col) =
                        __floats2half2_rn(ox, oy);
                }
            }
        }
    }
}

// ---------------- DistMult score: one warp per triple (fp16 h) ------------
__global__ void score_kernel(const float* __restrict__ rel_emb,
                             const int* __restrict__ head,
                             const int* __restrict__ rel,
                             const int* __restrict__ tail,
                             float* __restrict__ out) {
    int t    = (blockIdx.x * blockDim.x + threadIdx.x) >> 5;
    int lane = threadIdx.x & 31;
    if (t >= NTRIP) return;
    uint2 ar = reinterpret_cast<const uint2*>(
        g_h216 + (size_t)head[t] * DIM)[lane];
    uint2 br = reinterpret_cast<const uint2*>(
        g_h216 + (size_t)tail[t] * DIM)[lane];
    const float4 r = reinterpret_cast<const float4*>(
        rel_emb + (size_t)rel[t] * DIM)[lane];
    float2 a0 = __half22float2(*reinterpret_cast<__half2*>(&ar.x));
    float2 a1 = __half22float2(*reinterpret_cast<__half2*>(&ar.y));
    float2 b0 = __half22float2(*reinterpret_cast<__half2*>(&br.x));
    float2 b1 = __half22float2(*reinterpret_cast<__half2*>(&br.y));
    float s = a0.x * r.x * b0.x + a0.y * r.y * b0.y
            + a1.x * r.z * b1.x + a1.y * r.w * b1.y;
#pragma unroll
    for (int off = 16; off; off >>= 1)
        s += __shfl_xor_sync(0xFFFFFFFFu, s, off);
    if (lane == 0) out[t] = s;
}

// ---------------- launcher -------------------------------------------------
extern "C" void kernel_launch(void* const* d_in, const int* in_sizes, int n_in,
                              void* d_out, int out_size) {
    const float* emb   = (const float*)d_in[0];
    const float* W0    = (const float*)d_in[1];
    const float* root0 = (const float*)d_in[2];
    const float* b0    = (const float*)d_in[3];
    const float* W1    = (const float*)d_in[4];
    const float* root1 = (const float*)d_in[5];
    const float* b1    = (const float*)d_in[6];
    const float* relE  = (const float*)d_in[7];
    const int*   ei    = (const int*)d_in[8];
    const int*   et    = (const int*)d_in[9];
    const int*   hidx  = (const int*)d_in[10];
    const int*   ridx  = (const int*)d_in[11];
    const int*   tidx  = (const int*)d_in[12];
    float*       out   = (float*)d_out;

    static int smemSet = 0;
    if (!smemSet) {
        cudaFuncSetAttribute(rgcn_gemm_mma,
                             cudaFuncAttributeMaxDynamicSharedMemorySize,
                             SMEM_TOT);
        smemSet = 1;
    }

    const int edgeGrid  = (NEDGE + 255) / 256;          // 3125
    const int aggGrid   = (NSEG * 32 + 255) / 256;      // 50000
    const int gemmGrid  = (NNODES + 127) / 128;         // 391
    const int scoreGrid = (NTRIP * 32 + 255) / 256;     // 12500

    // one-time-per-call conversions (independent, cheap)
    conv_emb<<<4096, 256>>>(emb);
    transpose_w<<<2 * KTOT, 128>>>(W0, root0, W1, root1);

    // ----- CSR build (shared by both layers) -----
    csr_zero<<<1024, 256>>>();
    csr_hist<<<edgeGrid, 256>>>(ei, et);
    csr_off<<<NBLK, 1024>>>();
    csr_fill<<<edgeGrid, 256>>>(ei, et);

    // ----- layer 0 -----
    aggregate_kernel<<<aggGrid, 256>>>(0);
    rgcn_gemm_mma<<<gemmGrid, 256, SMEM_TOT>>>(0, /*wt*/0, b0, /*out*/0);

    // ----- layer 1 -----
    aggregate_kernel<<<aggGrid, 256>>>(1);
    rgcn_gemm_mma<<<gemmGrid, 256, SMEM_TOT>>>(1, /*wt*/1, b1, /*out*/1);

    // ----- DistMult score -----
    score_kernel<<<scoreGrid, 256>>>(relE, hidx, ridx, tidx, out);
}

// round 13
// speedup vs baseline: 1.2106x; 1.1021x over previous
#include <cuda_runtime.h>
#include <cuda_fp16.h>
#include <cstdint>

// Problem sizes (fixed by the reference)
#define NNODES 50000
#define NREL   8
#define DIM    128
#define NEDGE  800000
#define NTRIP  100000
#define KTOT   1152          // NREL*DIM + DIM (root folded as 9th block)
#define K0LIM  1024          // NREL*DIM
#define NSEG   (NNODES * NREL)          // 400000
#define NBLK   ((NSEG + 1023) / 1024)   // 391

// ---------------- scratch (static device globals; no allocs allowed) -------
__device__ __align__(16) __half g_sum16[(size_t)NSEG * DIM];     // 102.4 MB fp16 means
__device__ __align__(16) __half g_e16[(size_t)NNODES * DIM];     // 12.8 MB emb fp16
__device__ __align__(16) __half g_h116[(size_t)NNODES * DIM];    // 12.8 MB
__device__ __align__(16) __half g_h216[(size_t)NNODES * DIM];    // 12.8 MB
__device__ __align__(16) __half g_WT016[(size_t)DIM * KTOT];     // (W0||root0)^T fp16
__device__ __align__(16) __half g_WT116[(size_t)DIM * KTOT];
__device__ int g_cnt[NSEG];
__device__ int g_off[NSEG];
__device__ int g_fill[NSEG];
__device__ int g_csr[NEDGE];
__device__ int g_cursor;

__device__ __forceinline__ uint32_t smem_u32(const void* p) {
    uint32_t a;
    asm("{ .reg .u64 t; cvta.to.shared.u64 t, %1; cvt.u32.u64 %0, t; }"
        : "=r"(a) : "l"(p));
    return a;
}
__device__ __forceinline__ void cp16(uint32_t dst, const void* src, bool pred) {
    int sz = pred ? 16 : 0;
    asm volatile("cp.async.cg.shared.global [%0], [%1], 16, %2;"
                 :: "r"(dst), "l"(src), "r"(sz) : "memory");
}

// ---------------- emb -> fp16 ----------------------------------------------
__global__ void conv_emb(const float* __restrict__ emb) {
    const size_t n4 = (size_t)NNODES * DIM / 4;
    for (size_t i = (size_t)blockIdx.x * blockDim.x + threadIdx.x;
         i < n4; i += (size_t)gridDim.x * blockDim.x) {
        float4 v = reinterpret_cast<const float4*>(emb)[i];
        __half2 lo = __floats2half2_rn(v.x, v.y);
        __half2 hi = __floats2half2_rn(v.z, v.w);
        uint2 o;
        o.x = *reinterpret_cast<uint32_t*>(&lo);
        o.y = *reinterpret_cast<uint32_t*>(&hi);
        reinterpret_cast<uint2*>(g_e16)[i] = o;
    }
}

// ---------------- W||root transpose -> fp16 --------------------------------
__global__ void transpose_w(const float* __restrict__ W0,
                            const float* __restrict__ root0,
                            const float* __restrict__ W1,
                            const float* __restrict__ root1) {
    int b = blockIdx.x;
    int layer = b / KTOT;
    int k = b % KTOT;
    const float* src;
    if (layer == 0)
        src = (k < K0LIM) ? (W0 + (size_t)k * DIM) : (root0 + (size_t)(k - K0LIM) * DIM);
    else
        src = (k < K0LIM) ? (W1 + (size_t)k * DIM) : (root1 + (size_t)(k - K0LIM) * DIM);
    float v = src[threadIdx.x];
    __half* dst = layer ? g_WT116 : g_WT016;
    dst[(size_t)threadIdx.x * KTOT + k] = __float2half_rn(v);
}

// ---------------- CSR build -----------------------------------------------
__global__ void csr_zero() {
    for (int i = blockIdx.x * blockDim.x + threadIdx.x; i < NSEG;
         i += gridDim.x * blockDim.x) {
        g_cnt[i] = 0;
        g_fill[i] = 0;
    }
    if (blockIdx.x == 0 && threadIdx.x == 0) g_cursor = 0;
}
__global__ void csr_hist(const int* __restrict__ ei,
                         const int* __restrict__ et) {
    int e = blockIdx.x * blockDim.x + threadIdx.x;
    if (e >= NEDGE) return;
    int seg = ei[NEDGE + e] * NREL + et[e];
    atomicAdd(&g_cnt[seg], 1);
}
// single-kernel offsets: in-block inclusive scan + atomic cursor for base.
__global__ void csr_off() {  // grid NBLK x 1024
    __shared__ int sh[1024];
    __shared__ int sbase;
    int gid = blockIdx.x * 1024 + threadIdx.x;
    int v = (gid < NSEG) ? g_cnt[gid] : 0;
    sh[threadIdx.x] = v;
    __syncthreads();
    for (int ofs = 1; ofs < 1024; ofs <<= 1) {
        int t = (threadIdx.x >= ofs) ? sh[threadIdx.x - ofs] : 0;
        __syncthreads();
        sh[threadIdx.x] += t;
        __syncthreads();
    }
    if (threadIdx.x == 1023) sbase = atomicAdd(&g_cursor, sh[1023]);
    __syncthreads();
    if (gid < NSEG) g_off[gid] = sbase + sh[threadIdx.x] - v;
}
__global__ void csr_fill(const int* __restrict__ ei,
                         const int* __restrict__ et) {
    int e = blockIdx.x * blockDim.x + threadIdx.x;
    if (e >= NEDGE) return;
    int seg = ei[NEDGE + e] * NREL + et[e];
    int pos = g_off[seg] + atomicAdd(&g_fill[seg], 1);
    g_csr[pos] = ei[e];
}

// ---------------- aggregate: 2 segments per warp, interleaved gathers ------
// NSEG = 400000 (even) -> exactly NSEG/2 warps, no stragglers.
__global__ __launch_bounds__(256) void aggregate_kernel(int useG) {
    int w    = (blockIdx.x * blockDim.x + threadIdx.x) >> 5;
    int lane = threadIdx.x & 31;
    int sA = w * 2;
    if (sA >= NSEG) return;
    int sB = sA + 1;
    const __half* __restrict__ h = useG ? g_h116 : g_e16;

    int begA = g_off[sA], cA = g_cnt[sA];
    int begB = g_off[sB], cB = g_cnt[sB];
    float4 accA = make_float4(0.f, 0.f, 0.f, 0.f);
    float4 accB = make_float4(0.f, 0.f, 0.f, 0.f);
    int cmax = max(cA, cB);
    for (int base = 0; base < cmax; base += 4) {
        int iA[4], iB[4];
#pragma unroll
        for (int j = 0; j < 4; ++j) {
            iA[j] = (base + j < cA) ? g_csr[begA + base + j] : -1;
            iB[j] = (base + j < cB) ? g_csr[begB + base + j] : -1;
        }
#pragma unroll
        for (int j = 0; j < 4; ++j) {
            if (iA[j] >= 0) {
                uint2 t = reinterpret_cast<const uint2*>(
                    h + (size_t)iA[j] * DIM)[lane];
                float2 f0 = __half22float2(*reinterpret_cast<__half2*>(&t.x));
                float2 f1 = __half22float2(*reinterpret_cast<__half2*>(&t.y));
                accA.x += f0.x; accA.y += f0.y; accA.z += f1.x; accA.w += f1.y;
            }
            if (iB[j] >= 0) {
                uint2 t = reinterpret_cast<const uint2*>(
                    h + (size_t)iB[j] * DIM)[lane];
                float2 f0 = __half22float2(*reinterpret_cast<__half2*>(&t.x));
                float2 f1 = __half22float2(*reinterpret_cast<__half2*>(&t.y));
                accB.x += f0.x; accB.y += f0.y; accB.z += f1.x; accB.w += f1.y;
            }
        }
    }
    float invA = 1.0f / (float)max(cA, 1);
    float invB = 1.0f / (float)max(cB, 1);
    __half2 a0 = __floats2half2_rn(accA.x * invA, accA.y * invA);
    __half2 a1 = __floats2half2_rn(accA.z * invA, accA.w * invA);
    __half2 b0 = __floats2half2_rn(accB.x * invB, accB.y * invB);
    __half2 b1 = __floats2half2_rn(accB.z * invB, accB.w * invB);
    uint2 rA, rB;
    rA.x = *reinterpret_cast<uint32_t*>(&a0);
    rA.y = *reinterpret_cast<uint32_t*>(&a1);
    rB.x = *reinterpret_cast<uint32_t*>(&b0);
    rB.y = *reinterpret_cast<uint32_t*>(&b1);
    // plain stores: g_sum16 (102.4 MB) fits in L2 -> GEMM A-reads hit L2
    reinterpret_cast<uint2*>(g_sum16 + (size_t)sA * DIM)[lane] = rA;
    reinterpret_cast<uint2*>(g_sum16 + (size_t)sB * DIM)[lane] = rB;
}

// ---------------- fp16 mma.sync RGCN layer GEMM (cp.async pipeline) --------
// out[n,:] = relu( [g_sum16(means) || h16[n,:]] @ Wcat + bias )
// BM=128, BN=128, BK=64, 3-stage cp.async. 8 warps 4x2, warp tile 32x64.
#define KCH     64
#define NCHUNK  (KTOT / KCH)            // 18
#define LDPH    72                      // padded smem row stride (halfs)
#define BUF_H   (2 * 128 * LDPH)        // halfs per stage (A+B)
#define NSTAGE  3
#define SMEM_TOT (NSTAGE * BUF_H * 2)   // 110592 B

__device__ __forceinline__ void mma_f16(float* c, const uint32_t* a,
                                        const uint32_t* b) {
    asm volatile(
        "mma.sync.aligned.m16n8k16.row.col.f32.f16.f16.f32 "
        "{%0,%1,%2,%3}, {%4,%5,%6,%7}, {%8,%9}, {%0,%1,%2,%3};"
        : "+f"(c[0]), "+f"(c[1]), "+f"(c[2]), "+f"(c[3])
        : "r"(a[0]), "r"(a[1]), "r"(a[2]), "r"(a[3]), "r"(b[0]), "r"(b[1]));
}

__global__ __launch_bounds__(256, 2) void rgcn_gemm_mma(
    int useGin, int wtSel, const float* __restrict__ bias, int outSel)
{
    extern __shared__ __half smemh[];
    const uint32_t smemBase = smem_u32(smemh);
    const int tid  = threadIdx.x;
    const int wid  = tid >> 5;
    const int lane = tid & 31;
    const int g    = lane >> 2;
    const int t4   = lane & 3;
    const int wr   = wid & 3;        // warp row (M: 4 x 32)
    const int wc   = wid >> 2;       // warp col (N: 2 x 64)
    const int row0 = blockIdx.x * 128;

    const __half* __restrict__ hin = useGin ? g_h116 : g_e16;
    const __half* __restrict__ WT  = wtSel ? g_WT116 : g_WT016;
    __half* __restrict__ hout = outSel ? g_h216 : g_h116;

    float acc[2][8][4];
#pragma unroll
    for (int mt = 0; mt < 2; ++mt)
#pragma unroll
        for (int nt = 0; nt < 8; ++nt)
#pragma unroll
            for (int j = 0; j < 4; ++j) acc[mt][nt][j] = 0.f;

    // ---- issue cp.async loads for chunk c into stage buf ----
    auto issue = [&](int buf, int c) {
        const int k0 = c * KCH;
        const bool isSum = (k0 < K0LIM);
        uint32_t aBase = smemBase + (uint32_t)(buf * BUF_H) * 2u;
        uint32_t bBase = aBase + 128u * LDPH * 2u;
#pragma unroll
        for (int it = 0; it < 8; ++it) {
            int idx = tid + it * 256;        // 0..2047
            int m = (idx & 1023) >> 3;
            int q = idx & 7;
            uint32_t off = (uint32_t)(m * LDPH + q * 8) * 2u;
            if (idx < 1024) {
                int n = row0 + m;
                bool ok = (n < NNODES);
                int nc = ok ? n : (NNODES - 1);
                const __half* srcA = isSum
                    ? (g_sum16 + (size_t)nc * K0LIM + k0 + q * 8)
                    : (hin + (size_t)nc * DIM + (k0 - K0LIM) + q * 8);
                cp16(aBase + off, srcA, ok);
            } else {
                cp16(bBase + off, WT + (size_t)m * KTOT + k0 + q * 8, true);
            }
        }
        asm volatile("cp.async.commit_group;" ::: "memory");
    };

    // ---- compute one k-chunk (4 k16-steps) from stage buf ----
    auto compute = [&](int buf) {
        const __half* smA = smemh + buf * BUF_H;
        const __half* smB = smA + 128 * LDPH;
#pragma unroll
        for (int ks = 0; ks < 4; ++ks) {
            const int kk = ks * 16;
            uint32_t a[2][4], b[8][2];
#pragma unroll
            for (int mt = 0; mt < 2; ++mt) {
                int r0 = wr * 32 + mt * 16 + g;
                a[mt][0] = *reinterpret_cast<const uint32_t*>(
                    smA + (r0)     * LDPH + kk + 2 * t4);
                a[mt][1] = *reinterpret_cast<const uint32_t*>(
                    smA + (r0 + 8) * LDPH + kk + 2 * t4);
                a[mt][2] = *reinterpret_cast<const uint32_t*>(
                    smA + (r0)     * LDPH + kk + 8 + 2 * t4);
                a[mt][3] = *reinterpret_cast<const uint32_t*>(
                    smA + (r0 + 8) * LDPH + kk + 8 + 2 * t4);
            }
#pragma unroll
            for (int nt = 0; nt < 8; ++nt) {
                int nn = wc * 64 + nt * 8 + g;
                b[nt][0] = *reinterpret_cast<const uint32_t*>(
                    smB + nn * LDPH + kk + 2 * t4);
                b[nt][1] = *reinterpret_cast<const uint32_t*>(
                    smB + nn * LDPH + kk + 8 + 2 * t4);
            }
#pragma unroll
            for (int mt = 0; mt < 2; ++mt)
#pragma unroll
                for (int nt = 0; nt < 8; ++nt)
                    mma_f16(acc[mt][nt], a[mt], b[nt]);
        }
    };

    // ---- 3-stage pipeline ----
    issue(0, 0);
    issue(1, 1);
    for (int c = 0; c < NCHUNK; ++c) {
        if (c + 2 < NCHUNK) {
            issue((c + 2) % NSTAGE, c + 2);
            asm volatile("cp.async.wait_group 2;" ::: "memory");
        } else if (c + 1 < NCHUNK) {
            asm volatile("cp.async.wait_group 1;" ::: "memory");
        } else {
            asm volatile("cp.async.wait_group 0;" ::: "memory");
        }
        __syncthreads();
        compute(c % NSTAGE);
        __syncthreads();
    }

    // ---- epilogue: bias + relu, write fp16 ----
    float2 bb[8];
#pragma unroll
    for (int nt = 0; nt < 8; ++nt) {
        int col = wc * 64 + nt * 8 + t4 * 2;
        bb[nt].x = __ldg(bias + col);
        bb[nt].y = __ldg(bias + col + 1);
    }
#pragma unroll
    for (int mt = 0; mt < 2; ++mt) {
        int r0 = row0 + wr * 32 + mt * 16 + g;
#pragma unroll
        for (int half = 0; half < 2; ++half) {
            int n = r0 + half * 8;
            if (n < NNODES) {
                __half* dst = hout + (size_t)n * DIM;
#pragma unroll
                for (int nt = 0; nt < 8; ++nt) {
                    int col = wc * 64 + nt * 8 + t4 * 2;
                    float ox = fmaxf(acc[mt][nt][half * 2 + 0] + bb[nt].x, 0.f);
                    float oy = fmaxf(acc[mt][nt][half * 2 + 1] + bb[nt].y, 0.f);
                    *reinterpret_cast<__half2*>(dst + col) =
                        __floats2half2_rn(ox, oy);
                }
            }
        }
    }
}

// ---------------- DistMult score: one warp per triple (fp16 h) ------------
__global__ void score_kernel(const float* __restrict__ rel_emb,
                             const int* __restrict__ head,
                             const int* __restrict__ rel,
                             const int* __restrict__ tail,
                             float* __restrict__ out) {
    int t    = (blockIdx.x * blockDim.x + threadIdx.x) >> 5;
    int lane = threadIdx.x & 31;
    if (t >= NTRIP) return;
    uint2 ar = reinterpret_cast<const uint2*>(
        g_h216 + (size_t)head[t] * DIM)[lane];
    uint2 br = reinterpret_cast<const uint2*>(
        g_h216 + (size_t)tail[t] * DIM)[lane];
    const float4 r = reinterpret_cast<const float4*>(
        rel_emb + (size_t)rel[t] * DIM)[lane];
    float2 a0 = __half22float2(*reinterpret_cast<__half2*>(&ar.x));
    float2 a1 = __half22float2(*reinterpret_cast<__half2*>(&ar.y));
    float2 b0 = __half22float2(*reinterpret_cast<__half2*>(&br.x));
    float2 b1 = __half22float2(*reinterpret_cast<__half2*>(&br.y));
    float s = a0.x * r.x * b0.x + a0.y * r.y * b0.y
            + a1.x * r.z * b1.x + a1.y * r.w * b1.y;
#pragma unroll
    for (int off = 16; off; off >>= 1)
        s += __shfl_xor_sync(0xFFFFFFFFu, s, off);
    if (lane == 0) out[t] = s;
}

// ---------------- launcher -------------------------------------------------
extern "C" void kernel_launch(void* const* d_in, const int* in_sizes, int n_in,
                              void* d_out, int out_size) {
    const float* emb   = (const float*)d_in[0];
    const float* W0    = (const float*)d_in[1];
    const float* root0 = (const float*)d_in[2];
    const float* b0    = (const float*)d_in[3];
    const float* W1    = (const float*)d_in[4];
    const float* root1 = (const float*)d_in[5];
    const float* b1    = (const float*)d_in[6];
    const float* relE  = (const float*)d_in[7];
    const int*   ei    = (const int*)d_in[8];
    const int*   et    = (const int*)d_in[9];
    const int*   hidx  = (const int*)d_in[10];
    const int*   ridx  = (const int*)d_in[11];
    const int*   tidx  = (const int*)d_in[12];
    float*       out   = (float*)d_out;

    static int smemSet = 0;
    if (!smemSet) {
        cudaFuncSetAttribute(rgcn_gemm_mma,
                             cudaFuncAttributeMaxDynamicSharedMemorySize,
                             SMEM_TOT);
        smemSet = 1;
    }

    const int edgeGrid  = (NEDGE + 255) / 256;               // 3125
    const int aggGrid   = ((NSEG / 2) * 32 + 255) / 256;     // 25000
    const int gemmGrid  = (NNODES + 127) / 128;              // 391
    const int scoreGrid = (NTRIP * 32 + 255) / 256;          // 12500

    // one-time-per-call conversions (independent, cheap)
    conv_emb<<<4096, 256>>>(emb);
    transpose_w<<<2 * KTOT, 128>>>(W0, root0, W1, root1);

    // ----- CSR build (shared by both layers) -----
    csr_zero<<<1024, 256>>>();
    csr_hist<<<edgeGrid, 256>>>(ei, et);
    csr_off<<<NBLK, 1024>>>();
    csr_fill<<<edgeGrid, 256>>>(ei, et);

    // ----- layer 0 -----
    aggregate_kernel<<<aggGrid, 256>>>(0);
    rgcn_gemm_mma<<<gemmGrid, 256, SMEM_TOT>>>(0, /*wt*/0, b0, /*out*/0);

    // ----- layer 1 -----
    aggregate_kernel<<<aggGrid, 256>>>(1);
    rgcn_gemm_mma<<<gemmGrid, 256, SMEM_TOT>>>(1, /*wt*/1, b1, /*out*/1);

    // ----- DistMult score -----
    score_kernel<<<scoreGrid, 256>>>(relE, hidx, ridx, tidx, out);
}

// round 14
// speedup vs baseline: 1.2777x; 1.0554x over previous
#include <cuda_runtime.h>
#include <cuda_fp16.h>
#include <cstdint>

// Problem sizes (fixed by the reference)
#define NNODES 50000
#define NREL   8
#define DIM    128
#define NEDGE  800000
#define NTRIP  100000
#define KTOT   1152          // NREL*DIM + DIM (root folded as 9th block)
#define K0LIM  1024          // NREL*DIM
#define NSEG   (NNODES * NREL)          // 400000
#define NBLK   ((NSEG + 1023) / 1024)   // 391

// ---------------- scratch (static device globals; no allocs allowed) -------
__device__ __align__(16) __half g_sum16[(size_t)NSEG * DIM];     // 102.4 MB fp16 means
__device__ __align__(16) __half g_e16[(size_t)NNODES * DIM];     // 12.8 MB emb fp16
__device__ __align__(16) __half g_h116[(size_t)NNODES * DIM];    // 12.8 MB
__device__ __align__(16) __half g_h216[(size_t)NNODES * DIM];    // 12.8 MB
__device__ __align__(16) __half g_WT016[(size_t)DIM * KTOT];     // (W0||root0)^T fp16
__device__ __align__(16) __half g_WT116[(size_t)DIM * KTOT];
__device__ int g_cnt[NSEG];
__device__ int g_off[NSEG];
__device__ int g_fill[NSEG];
__device__ int g_csr[NEDGE];
__device__ int g_cursor;

__device__ __forceinline__ uint32_t smem_u32(const void* p) {
    uint32_t a;
    asm("{ .reg .u64 t; cvta.to.shared.u64 t, %1; cvt.u32.u64 %0, t; }"
        : "=r"(a) : "l"(p));
    return a;
}
__device__ __forceinline__ void cp16(uint32_t dst, const void* src, bool pred) {
    int sz = pred ? 16 : 0;
    asm volatile("cp.async.cg.shared.global [%0], [%1], 16, %2;"
                 :: "r"(dst), "l"(src), "r"(sz) : "memory");
}

// ---------------- fused prep: emb->fp16, W transpose, cnt zero -------------
#define PREP_CONV 3200            // conv blocks: 3200 x 256 thr x 2 uint2
#define PREP_TW   (2 * KTOT)      // 2304 transpose blocks
#define PREP_Z    391             // cnt-zero blocks
__global__ void prep_kernel(const float* __restrict__ emb,
                            const float* __restrict__ W0,
                            const float* __restrict__ root0,
                            const float* __restrict__ W1,
                            const float* __restrict__ root1) {
    int b = blockIdx.x;
    if (b < PREP_CONV) {
        const size_t n4 = (size_t)NNODES * DIM / 4;    // 1.6M uint2
        for (size_t i = (size_t)b * 512 + threadIdx.x;
             i < n4 && i < (size_t)(b + 1) * 512; i += 256) {
            float4 v = reinterpret_cast<const float4*>(emb)[i];
            __half2 lo = __floats2half2_rn(v.x, v.y);
            __half2 hi = __floats2half2_rn(v.z, v.w);
            uint2 o;
            o.x = *reinterpret_cast<uint32_t*>(&lo);
            o.y = *reinterpret_cast<uint32_t*>(&hi);
            reinterpret_cast<uint2*>(g_e16)[i] = o;
        }
    } else if (b < PREP_CONV + PREP_TW) {
        if (threadIdx.x < 128) {
            int bb = b - PREP_CONV;
            int layer = bb / KTOT;
            int k = bb % KTOT;
            const float* src;
            if (layer == 0)
                src = (k < K0LIM) ? (W0 + (size_t)k * DIM)
                                  : (root0 + (size_t)(k - K0LIM) * DIM);
            else
                src = (k < K0LIM) ? (W1 + (size_t)k * DIM)
                                  : (root1 + (size_t)(k - K0LIM) * DIM);
            float v = src[threadIdx.x];
            __half* dst = layer ? g_WT116 : g_WT016;
            dst[(size_t)threadIdx.x * KTOT + k] = __float2half_rn(v);
        }
    } else {
        int bb = b - PREP_CONV - PREP_TW;
        for (int i = bb * 1024 + threadIdx.x;
             i < NSEG && i < (bb + 1) * 1024; i += 256)
            g_cnt[i] = 0;
        if (bb == 0 && threadIdx.x == 0) g_cursor = 0;
    }
}

// ---------------- CSR build -----------------------------------------------
__global__ void csr_hist(const int* __restrict__ ei,
                         const int* __restrict__ et) {
    int e = blockIdx.x * blockDim.x + threadIdx.x;
    if (e >= NEDGE) return;
    int seg = ei[NEDGE + e] * NREL + et[e];
    atomicAdd(&g_cnt[seg], 1);
}
// single-kernel offsets: in-block inclusive scan + atomic cursor for base.
// Also zeroes g_fill (touches the same indices anyway).
__global__ void csr_off() {  // grid NBLK x 1024
    __shared__ int sh[1024];
    __shared__ int sbase;
    int gid = blockIdx.x * 1024 + threadIdx.x;
    int v = (gid < NSEG) ? g_cnt[gid] : 0;
    sh[threadIdx.x] = v;
    __syncthreads();
    for (int ofs = 1; ofs < 1024; ofs <<= 1) {
        int t = (threadIdx.x >= ofs) ? sh[threadIdx.x - ofs] : 0;
        __syncthreads();
        sh[threadIdx.x] += t;
        __syncthreads();
    }
    if (threadIdx.x == 1023) sbase = atomicAdd(&g_cursor, sh[1023]);
    __syncthreads();
    if (gid < NSEG) {
        g_off[gid] = sbase + sh[threadIdx.x] - v;
        g_fill[gid] = 0;
    }
}
__global__ void csr_fill(const int* __restrict__ ei,
                         const int* __restrict__ et) {
    int e = blockIdx.x * blockDim.x + threadIdx.x;
    if (e >= NEDGE) return;
    int seg = ei[NEDGE + e] * NREL + et[e];
    int pos = g_off[seg] + atomicAdd(&g_fill[seg], 1);
    g_csr[pos] = ei[e];
}

// ---------------- aggregate: 4 segments per warp, 2-deep batches -----------
// NSEG = 400000 (mult of 4) -> exactly NSEG/4 warps. The 4 segments share
// one dst node (rels 4w..4w+3): descriptor loads hit the same lines.
__global__ __launch_bounds__(256) void aggregate_kernel(int useG) {
    int w    = (blockIdx.x * blockDim.x + threadIdx.x) >> 5;
    int lane = threadIdx.x & 31;
    int s0 = w * 4;
    if (s0 >= NSEG) return;
    const __half* __restrict__ h = useG ? g_h116 : g_e16;

    int beg[4], c[4];
    float4 acc[4];
#pragma unroll
    for (int j = 0; j < 4; ++j) {
        beg[j] = g_off[s0 + j];
        c[j]   = g_cnt[s0 + j];
        acc[j] = make_float4(0.f, 0.f, 0.f, 0.f);
    }
    int cmax = max(max(c[0], c[1]), max(c[2], c[3]));
    for (int base = 0; base < cmax; base += 2) {
        int idx[4][2];
#pragma unroll
        for (int j = 0; j < 4; ++j)
#pragma unroll
            for (int k = 0; k < 2; ++k)
                idx[j][k] = (base + k < c[j]) ? g_csr[beg[j] + base + k] : -1;
#pragma unroll
        for (int j = 0; j < 4; ++j)
#pragma unroll
            for (int k = 0; k < 2; ++k) {
                if (idx[j][k] >= 0) {
                    uint2 t = reinterpret_cast<const uint2*>(
                        h + (size_t)idx[j][k] * DIM)[lane];
                    float2 f0 = __half22float2(*reinterpret_cast<__half2*>(&t.x));
                    float2 f1 = __half22float2(*reinterpret_cast<__half2*>(&t.y));
                    acc[j].x += f0.x; acc[j].y += f0.y;
                    acc[j].z += f1.x; acc[j].w += f1.y;
                }
            }
    }
#pragma unroll
    for (int j = 0; j < 4; ++j) {
        float inv = 1.0f / (float)max(c[j], 1);
        __half2 o0 = __floats2half2_rn(acc[j].x * inv, acc[j].y * inv);
        __half2 o1 = __floats2half2_rn(acc[j].z * inv, acc[j].w * inv);
        uint2 r;
        r.x = *reinterpret_cast<uint32_t*>(&o0);
        r.y = *reinterpret_cast<uint32_t*>(&o1);
        reinterpret_cast<uint2*>(g_sum16 + (size_t)(s0 + j) * DIM)[lane] = r;
    }
}

// ---------------- fp16 mma.sync RGCN layer GEMM (cp.async pipeline) --------
// out[n,:] = relu( [g_sum16(means) || h16[n,:]] @ Wcat + bias )
// BM=128, BN=128, BK=64, 3-stage cp.async. 8 warps 4x2, warp tile 32x64.
#define KCH     64
#define NCHUNK  (KTOT / KCH)            // 18
#define LDPH    72                      // padded smem row stride (halfs)
#define BUF_H   (2 * 128 * LDPH)        // halfs per stage (A+B)
#define NSTAGE  3
#define SMEM_TOT (NSTAGE * BUF_H * 2)   // 110592 B

__device__ __forceinline__ void mma_f16(float* c, const uint32_t* a,
                                        const uint32_t* b) {
    asm volatile(
        "mma.sync.aligned.m16n8k16.row.col.f32.f16.f16.f32 "
        "{%0,%1,%2,%3}, {%4,%5,%6,%7}, {%8,%9}, {%0,%1,%2,%3};"
        : "+f"(c[0]), "+f"(c[1]), "+f"(c[2]), "+f"(c[3])
        : "r"(a[0]), "r"(a[1]), "r"(a[2]), "r"(a[3]), "r"(b[0]), "r"(b[1]));
}

__global__ __launch_bounds__(256, 2) void rgcn_gemm_mma(
    int useGin, int wtSel, const float* __restrict__ bias, int outSel)
{
    extern __shared__ __half smemh[];
    const uint32_t smemBase = smem_u32(smemh);
    const int tid  = threadIdx.x;
    const int wid  = tid >> 5;
    const int lane = tid & 31;
    const int g    = lane >> 2;
    const int t4   = lane & 3;
    const int wr   = wid & 3;        // warp row (M: 4 x 32)
    const int wc   = wid >> 2;       // warp col (N: 2 x 64)
    const int row0 = blockIdx.x * 128;

    const __half* __restrict__ hin = useGin ? g_h116 : g_e16;
    const __half* __restrict__ WT  = wtSel ? g_WT116 : g_WT016;
    __half* __restrict__ hout = outSel ? g_h216 : g_h116;

    float acc[2][8][4];
#pragma unroll
    for (int mt = 0; mt < 2; ++mt)
#pragma unroll
        for (int nt = 0; nt < 8; ++nt)
#pragma unroll
            for (int j = 0; j < 4; ++j) acc[mt][nt][j] = 0.f;

    // ---- issue cp.async loads for chunk c into stage buf ----
    auto issue = [&](int buf, int c) {
        const int k0 = c * KCH;
        const bool isSum = (k0 < K0LIM);
        uint32_t aBase = smemBase + (uint32_t)(buf * BUF_H) * 2u;
        uint32_t bBase = aBase + 128u * LDPH * 2u;
#pragma unroll
        for (int it = 0; it < 8; ++it) {
            int idx = tid + it * 256;        // 0..2047
            int m = (idx & 1023) >> 3;
            int q = idx & 7;
            uint32_t off = (uint32_t)(m * LDPH + q * 8) * 2u;
            if (idx < 1024) {
                int n = row0 + m;
                bool ok = (n < NNODES);
                int nc = ok ? n : (NNODES - 1);
                const __half* srcA = isSum
                    ? (g_sum16 + (size_t)nc * K0LIM + k0 + q * 8)
                    : (hin + (size_t)nc * DIM + (k0 - K0LIM) + q * 8);
                cp16(aBase + off, srcA, ok);
            } else {
                cp16(bBase + off, WT + (size_t)m * KTOT + k0 + q * 8, true);
            }
        }
        asm volatile("cp.async.commit_group;" ::: "memory");
    };

    // ---- compute one k-chunk (4 k16-steps) from stage buf ----
    auto compute = [&](int buf) {
        const __half* smA = smemh + buf * BUF_H;
        const __half* smB = smA + 128 * LDPH;
#pragma unroll
        for (int ks = 0; ks < 4; ++ks) {
            const int kk = ks * 16;
            uint32_t a[2][4], b[8][2];
#pragma unroll
            for (int mt = 0; mt < 2; ++mt) {
                int r0 = wr * 32 + mt * 16 + g;
                a[mt][0] = *reinterpret_cast<const uint32_t*>(
                    smA + (r0)     * LDPH + kk + 2 * t4);
                a[mt][1] = *reinterpret_cast<const uint32_t*>(
                    smA + (r0 + 8) * LDPH + kk + 2 * t4);
                a[mt][2] = *reinterpret_cast<const uint32_t*>(
                    smA + (r0)     * LDPH + kk + 8 + 2 * t4);
                a[mt][3] = *reinterpret_cast<const uint32_t*>(
                    smA + (r0 + 8) * LDPH + kk + 8 + 2 * t4);
            }
#pragma unroll
            for (int nt = 0; nt < 8; ++nt) {
                int nn = wc * 64 + nt * 8 + g;
                b[nt][0] = *reinterpret_cast<const uint32_t*>(
                    smB + nn * LDPH + kk + 2 * t4);
                b[nt][1] = *reinterpret_cast<const uint32_t*>(
                    smB + nn * LDPH + kk + 8 + 2 * t4);
            }
#pragma unroll
            for (int mt = 0; mt < 2; ++mt)
#pragma unroll
                for (int nt = 0; nt < 8; ++nt)
                    mma_f16(acc[mt][nt], a[mt], b[nt]);
        }
    };

    // ---- 3-stage pipeline ----
    issue(0, 0);
    issue(1, 1);
    for (int c = 0; c < NCHUNK; ++c) {
        if (c + 2 < NCHUNK) {
            issue((c + 2) % NSTAGE, c + 2);
            asm volatile("cp.async.wait_group 2;" ::: "memory");
        } else if (c + 1 < NCHUNK) {
            asm volatile("cp.async.wait_group 1;" ::: "memory");
        } else {
            asm volatile("cp.async.wait_group 0;" ::: "memory");
        }
        __syncthreads();
        compute(c % NSTAGE);
        __syncthreads();
    }

    // ---- epilogue: bias + relu, write fp16 ----
    float2 bb[8];
#pragma unroll
    for (int nt = 0; nt < 8; ++nt) {
        int col = wc * 64 + nt * 8 + t4 * 2;
        bb[nt].x = __ldg(bias + col);
        bb[nt].y = __ldg(bias + col + 1);
    }
#pragma unroll
    for (int mt = 0; mt < 2; ++mt) {
        int r0 = row0 + wr * 32 + mt * 16 + g;
#pragma unroll
        for (int half = 0; half < 2; ++half) {
            int n = r0 + half * 8;
            if (n < NNODES) {
                __half* dst = hout + (size_t)n * DIM;
#pragma unroll
                for (int nt = 0; nt < 8; ++nt) {
                    int col = wc * 64 + nt * 8 + t4 * 2;
                    float ox = fmaxf(acc[mt][nt][half * 2 + 0] + bb[nt].x, 0.f);
                    float oy = fmaxf(acc[mt][nt][half * 2 + 1] + bb[nt].y, 0.f);
                    *reinterpret_cast<__half2*>(dst + col) =
                        __floats2half2_rn(ox, oy);
                }
            }
        }
    }
}

// ---------------- DistMult score: 2 triples per warp (fp16 h) --------------
__global__ void score_kernel(const float* __restrict__ rel_emb,
                             const int* __restrict__ head,
                             const int* __restrict__ rel,
                             const int* __restrict__ tail,
                             float* __restrict__ out) {
    int w    = (blockIdx.x * blockDim.x + threadIdx.x) >> 5;
    int lane = threadIdx.x & 31;
    int t0 = w * 2;
    if (t0 >= NTRIP) return;
    int t1 = min(t0 + 1, NTRIP - 1);

    int h0 = head[t0], h1 = head[t1];
    int l0 = tail[t0], l1 = tail[t1];
    int r0i = rel[t0],  r1i = rel[t1];

    uint2 a0r = reinterpret_cast<const uint2*>(g_h216 + (size_t)h0 * DIM)[lane];
    uint2 a1r = reinterpret_cast<const uint2*>(g_h216 + (size_t)h1 * DIM)[lane];
    uint2 b0r = reinterpret_cast<const uint2*>(g_h216 + (size_t)l0 * DIM)[lane];
    uint2 b1r = reinterpret_cast<const uint2*>(g_h216 + (size_t)l1 * DIM)[lane];
    float4 r0 = reinterpret_cast<const float4*>(rel_emb + (size_t)r0i * DIM)[lane];
    float4 r1 = reinterpret_cast<const float4*>(rel_emb + (size_t)r1i * DIM)[lane];

    float2 a00 = __half22float2(*reinterpret_cast<__half2*>(&a0r.x));
    float2 a01 = __half22float2(*reinterpret_cast<__half2*>(&a0r.y));
    float2 b00 = __half22float2(*reinterpret_cast<__half2*>(&b0r.x));
    float2 b01 = __half22float2(*reinterpret_cast<__half2*>(&b0r.y));
    float2 a10 = __half22float2(*reinterpret_cast<__half2*>(&a1r.x));
    float2 a11 = __half22float2(*reinterpret_cast<__half2*>(&a1r.y));
    float2 b10 = __half22float2(*reinterpret_cast<__half2*>(&b1r.x));
    float2 b11 = __half22float2(*reinterpret_cast<__half2*>(&b1r.y));

    float s0 = a00.x * r0.x * b00.x + a00.y * r0.y * b00.y
             + a01.x * r0.z * b01.x + a01.y * r0.w * b01.y;
    float s1 = a10.x * r1.x * b10.x + a10.y * r1.y * b10.y
             + a11.x * r1.z * b11.x + a11.y * r1.w * b11.y;
#pragma unroll
    for (int off = 16; off; off >>= 1) {
        s0 += __shfl_xor_sync(0xFFFFFFFFu, s0, off);
        s1 += __shfl_xor_sync(0xFFFFFFFFu, s1, off);
    }
    if (lane == 0) {
        out[t0] = s0;
        if (t1 > t0) out[t1] = s1;
    }
}

// ---------------- launcher -------------------------------------------------
extern "C" void kernel_launch(void* const* d_in, const int* in_sizes, int n_in,
                              void* d_out, int out_size) {
    const float* emb   = (const float*)d_in[0];
    const float* W0    = (const float*)d_in[1];
    const float* root0 = (const float*)d_in[2];
    const float* b0    = (const float*)d_in[3];
    const float* W1    = (const float*)d_in[4];
    const float* root1 = (const float*)d_in[5];
    const float* b1    = (const float*)d_in[6];
    const float* relE  = (const float*)d_in[7];
    const int*   ei    = (const int*)d_in[8];
    const int*   et    = (const int*)d_in[9];
    const int*   hidx  = (const int*)d_in[10];
    const int*   ridx  = (const int*)d_in[11];
    const int*   tidx  = (const int*)d_in[12];
    float*       out   = (float*)d_out;

    static int smemSet = 0;
    if (!smemSet) {
        cudaFuncSetAttribute(rgcn_gemm_mma,
                             cudaFuncAttributeMaxDynamicSharedMemorySize,
                             SMEM_TOT);
        smemSet = 1;
    }

    const int prepGrid  = PREP_CONV + PREP_TW + PREP_Z;       // 5895
    const int edgeGrid  = (NEDGE + 255) / 256;                // 3125
    const int aggGrid   = ((NSEG / 4) * 32 + 255) / 256;      // 12500
    const int gemmGrid  = (NNODES + 127) / 128;               // 391
    const int scoreGrid = (((NTRIP + 1) / 2) * 32 + 255) / 256; // 6250

    prep_kernel<<<prepGrid, 256>>>(emb, W0, root0, W1, root1);

    // ----- CSR build (shared by both layers) -----
    csr_hist<<<edgeGrid, 256>>>(ei, et);
    csr_off<<<NBLK, 1024>>>();
    csr_fill<<<edgeGrid, 256>>>(ei, et);

    // ----- layer 0 -----
    aggregate_kernel<<<aggGrid, 256>>>(0);
    rgcn_gemm_mma<<<gemmGrid, 256, SMEM_TOT>>>(0, /*wt*/0, b0, /*out*/0);

    // ----- layer 1 -----
    aggregate_kernel<<<aggGrid, 256>>>(1);
    rgcn_gemm_mma<<<gemmGrid, 256, SMEM_TOT>>>(1, /*wt*/1, b1, /*out*/1);

    // ----- DistMult score -----
    score_kernel<<<scoreGrid, 256>>>(relE, hidx, ridx, tidx, out);
}